// round 2
// baseline (speedup 1.0000x reference)
#include <cuda_runtime.h>

#define IN_DIM   128
#define OUT_DIM  128
#define N_NEIGH  32
#define BATCH    8192
#define WPB      8                      // warps per block
#define THREADS  (WPB * 32)

// Folded vectors: v1 = W^T u1, v2 = W^T u2, c = b.(u1+u2)
__device__ float g_v1[IN_DIM];
__device__ float g_v2[IN_DIM];
__device__ float g_c;

__global__ void prep_kernel(const float* __restrict__ W_w,
                            const float* __restrict__ W_b,
                            const float* __restrict__ u) {
    int i = threadIdx.x;                // 0..127: one input-dim column each
    float s1 = 0.f, s2 = 0.f;
    #pragma unroll 8
    for (int o = 0; o < OUT_DIM; o++) {
        float w = W_w[o * IN_DIM + i];  // coalesced across threads
        s1 += w * u[o];
        s2 += w * u[OUT_DIM + o];
    }
    g_v1[i] = s1;
    g_v2[i] = s2;
    if (i == 0) {
        float c = 0.f;
        #pragma unroll 8
        for (int o = 0; o < OUT_DIM; o++)
            c += W_b[o] * (u[o] + u[OUT_DIM + o]);
        g_c = c;
    }
}

__global__ __launch_bounds__(THREADS)
void gat_attn_kernel(const float* __restrict__ ai_sq,
                     const float* __restrict__ ai_sn,
                     float* __restrict__ out) {
    const int tid  = threadIdx.x;
    const int lane = tid & 31;
    const int warp = tid >> 5;

    __shared__ float sv1[IN_DIM];
    __shared__ float sv2[IN_DIM];
    __shared__ float sc;
    __shared__ float sbeta[N_NEIGH][WPB + 1];   // +1 pad: conflict-free
    if (tid < IN_DIM) { sv1[tid] = g_v1[tid]; sv2[tid] = g_v2[tid]; }
    if (tid == 0)     sc = g_c;
    __syncthreads();

    const int b0 = blockIdx.x * WPB;            // block's batch base
    const int b  = b0 + warp;                   // one warp per batch elem

    // Lane l owns input-dim slice [4l, 4l+4)
    const float4 v1r = *reinterpret_cast<const float4*>(&sv1[lane * 4]);
    const float4 v2r = *reinterpret_cast<const float4*>(&sv2[lane * 4]);

    // --- base term: ai_sq[b] . v1 + c (butterfly -> broadcast) ---
    const float4* sq = reinterpret_cast<const float4*>(ai_sq) + (size_t)b * (IN_DIM / 4);
    float4 a = sq[lane];
    float p = a.x * v1r.x + a.y * v1r.y + a.z * v1r.z + a.w * v1r.w;
    #pragma unroll
    for (int o = 16; o; o >>= 1) p += __shfl_xor_sync(0xffffffffu, p, o);
    const float base = p + sc;

    // --- 32 neighbor partial dots: load-first for MLP ---
    const size_t NSTR = (size_t)BATCH * (IN_DIM / 4);   // float4 neighbor stride
    const float4* sn = reinterpret_cast<const float4*>(ai_sn)
                       + (size_t)b * (IN_DIM / 4) + lane;

    float v[N_NEIGH];
    #pragma unroll
    for (int n = 0; n < N_NEIGH; n++) {
        float4 x = sn[(size_t)n * NSTR];
        v[n] = x.x * v2r.x + x.y * v2r.y + x.z * v2r.z + x.w * v2r.w;
    }

    // --- recursive-halving 32x32 transpose-reduce: 31 shuffles total.
    // After this, lane l holds mult[l,b] partial (full cross-lane sum of v[l]).
    #pragma unroll
    for (int off = 16; off; off >>= 1) {
        const bool hi = (lane & off) != 0;
        #pragma unroll
        for (int j = 0; j < off; j++) {
            float keep = hi ? v[j + off] : v[j];
            float send = hi ? v[j]       : v[j + off];
            v[j] = keep + __shfl_xor_sync(0xffffffffu, send, off);
        }
    }
    float m = v[0] + base;

    // leaky_relu(0.01) -> exp -> 32-way softmax across lanes
    float lr   = (m >= 0.f) ? m : 0.01f * m;
    float beta = expf(lr);
    float s = beta;
    #pragma unroll
    for (int o = 16; o; o >>= 1) s += __shfl_xor_sync(0xffffffffu, s, o);

    sbeta[lane][warp] = beta / s;
    __syncthreads();

    // Coalesced store: out[n, b0:b0+8] as one 32B segment per 8 threads.
    const int n = tid >> 3;        // 0..31
    const int j = tid & 7;         // 0..7
    out[(size_t)n * BATCH + b0 + j] = sbeta[n][j];
}

extern "C" void kernel_launch(void* const* d_in, const int* in_sizes, int n_in,
                              void* d_out, int out_size) {
    const float* ai_sq = (const float*)d_in[0];
    const float* ai_sn = (const float*)d_in[1];
    const float* W_w   = (const float*)d_in[2];
    const float* W_b   = (const float*)d_in[3];
    const float* u     = (const float*)d_in[4];
    float* out = (float*)d_out;

    prep_kernel<<<1, 128>>>(W_w, W_b, u);
    gat_attn_kernel<<<BATCH / WPB, THREADS>>>(ai_sq, ai_sn, out);
}

// round 3
// speedup vs baseline: 1.1982x; 1.1982x over previous
#include <cuda_runtime.h>

#define IN_DIM   128
#define OUT_DIM  128
#define N_NEIGH  32
#define BATCH    8192
#define WPB      8
#define THREADS  (WPB * 32)

__global__ __launch_bounds__(THREADS, 6)
void gat_fused_kernel(const float* __restrict__ ai_sq,
                      const float* __restrict__ ai_sn,
                      const float* __restrict__ W_w,
                      const float* __restrict__ W_b,
                      const float* __restrict__ u,
                      float* __restrict__ out)
{
    __shared__ float spart[WPB][N_NEIGH][32];   // 32 KB: per-warp partial-dot matrix
    __shared__ float sv1[IN_DIM], sv2[IN_DIM];  // folded vectors
    __shared__ float sbeta[N_NEIGH][WPB + 1];   // output staging (padded)
    __shared__ float sc;

    const int tid  = threadIdx.x;
    const int lane = tid & 31;
    const int warp = tid >> 5;

    // ---------- fused prep: v1 = W^T u1, v2 = W^T u2, c = b.(u1+u2) ----------
    // o-range split across two 128-thread halves to halve the latency chain.
    {
        const int i  = tid & 127;        // input dim owned by this thread
        const int o0 = (tid >> 7) * 64;  // o-half
        float s1 = 0.f, s2 = 0.f;
        #pragma unroll 8
        for (int k = 0; k < 64; k++) {
            const int o = o0 + k;
            const float w = W_w[o * IN_DIM + i];   // coalesced; L2-hot after wave 1
            s1 += w * u[o];
            s2 += w * u[OUT_DIM + o];
        }
        float* tmp = &spart[0][0][0];    // reuse spart as prep scratch
        tmp[tid]           = s1;
        tmp[THREADS + tid] = s2;

        float cpart = 0.f;               // warp 7 computes the bias term
        if (warp == 7) {
            #pragma unroll
            for (int k = 0; k < 4; k++) {
                const int o = lane + 32 * k;
                cpart += W_b[o] * (u[o] + u[OUT_DIM + o]);
            }
            #pragma unroll
            for (int off = 16; off; off >>= 1)
                cpart += __shfl_xor_sync(0xffffffffu, cpart, off);
        }
        __syncthreads();
        if (tid < IN_DIM) {
            sv1[tid] = tmp[tid] + tmp[tid + 128];
            sv2[tid] = tmp[THREADS + tid] + tmp[THREADS + tid + 128];
        }
        if (tid == 7 * 32) sc = cpart;
        __syncthreads();
    }

    // ---------- main: one warp per batch element ----------
    const int b0 = blockIdx.x * WPB;
    const int b  = b0 + warp;

    const float4 v1r = *reinterpret_cast<const float4*>(&sv1[lane * 4]);
    const float4 v2r = *reinterpret_cast<const float4*>(&sv2[lane * 4]);

    // base term: ai_sq[b] . v1 + c
    const float4* sq = reinterpret_cast<const float4*>(ai_sq) + (size_t)b * (IN_DIM / 4);
    float4 a = sq[lane];
    float p = a.x * v1r.x + a.y * v1r.y + a.z * v1r.z + a.w * v1r.w;
    #pragma unroll
    for (int off = 16; off; off >>= 1) p += __shfl_xor_sync(0xffffffffu, p, off);
    const float base = p + sc;

    // 32 neighbor partial dots -> smem (short register lifetime => deep MLP)
    const size_t NSTR = (size_t)BATCH * (IN_DIM / 4);
    const float4* sn = reinterpret_cast<const float4*>(ai_sn)
                       + (size_t)b * (IN_DIM / 4) + lane;
    float* myrow = &spart[warp][0][0];
    #pragma unroll
    for (int n = 0; n < N_NEIGH; n++) {
        float4 x = sn[(size_t)n * NSTR];
        myrow[n * 32 + lane] = x.x * v2r.x + x.y * v2r.y + x.z * v2r.z + x.w * v2r.w;
    }
    __syncwarp();

    // lane l sums row l with rotated column order -> conflict-free, no padding
    float m = 0.f;
    const float* r = &spart[warp][lane][0];
    #pragma unroll
    for (int j = 0; j < 32; j++) m += r[(j + lane) & 31];
    m += base;

    // leaky_relu(0.01) -> exp -> 32-way softmax across lanes
    const float lr   = (m >= 0.f) ? m : 0.01f * m;
    const float beta = expf(lr);
    float s = beta;
    #pragma unroll
    for (int off = 16; off; off >>= 1) s += __shfl_xor_sync(0xffffffffu, s, off);

    sbeta[lane][warp] = beta / s;
    __syncthreads();

    // coalesced store: out[n, b0:b0+8] in 32B segments
    const int n = tid >> 3;
    const int j = tid & 7;
    out[(size_t)n * BATCH + b0 + j] = sbeta[n][j];
}

extern "C" void kernel_launch(void* const* d_in, const int* in_sizes, int n_in,
                              void* d_out, int out_size) {
    const float* ai_sq = (const float*)d_in[0];
    const float* ai_sn = (const float*)d_in[1];
    const float* W_w   = (const float*)d_in[2];
    const float* W_b   = (const float*)d_in[3];
    const float* u     = (const float*)d_in[4];
    float* out = (float*)d_out;

    gat_fused_kernel<<<BATCH / WPB, THREADS>>>(ai_sq, ai_sn, W_w, W_b, u, out);
}